// round 2
// baseline (speedup 1.0000x reference)
#include <cuda_runtime.h>
#include <cstdint>
#include <cstddef>

#define SEQ   512
#define NBAT  256
#define IN_DIM 256
#define HID   1024
#define NCLS  128

// ---------------- scratch (no allocation allowed -> device globals) ----------
static __device__ float d_xfp[(size_t)SEQ * NBAT * HID];  // bf + emb@Wfx^T
static __device__ float d_xip[(size_t)SEQ * NBAT * HID];  // bi + emb@Wix^T
static __device__ float d_g  [(size_t)SEQ * NBAT * HID];  // sigmoid(bc + emb@Wcx^T)
static __device__ float d_c0[NBAT * HID];
static __device__ float d_c1[NBAT * HID];
static __device__ float d_hT[NBAT * HID];

__device__ __forceinline__ float sigf(float x) { return 1.0f / (1.0f + __expf(-x)); }

// ---------------- Phase A: x-projections for all timesteps -------------------
// out[m][h], m = s*256 + b, h in [0,1024); A row = emb[x[b][s]] (K=256)
// out_sel: 0 -> d_xfp, 1 -> d_xip, 2 -> d_g (with sigmoid)
__global__ void __launch_bounds__(256) phaseA_kernel(
    const int* __restrict__ x, const float* __restrict__ emb,
    const float* __restrict__ W, const float* __restrict__ bias, int out_sel)
{
    __shared__ float As[128][33];
    __shared__ float Bs[64][33];
    __shared__ int   idx[128];
    const int tid = threadIdx.x;
    const int m0 = blockIdx.x * 128;
    const int n0 = blockIdx.y * 64;

    if (tid < 128) {
        int m = m0 + tid;
        int s = m >> 8;        // m = s*256 + b
        int b = m & 255;
        idx[tid] = x[b * SEQ + s];
    }
    __syncthreads();

    float acc[8][4];
#pragma unroll
    for (int i = 0; i < 8; i++)
#pragma unroll
        for (int j = 0; j < 4; j++) acc[i][j] = 0.0f;

    const int mt = (tid >> 4) * 8;   // 0..120
    const int nt = (tid & 15) * 4;   // 0..60

    for (int k0 = 0; k0 < IN_DIM; k0 += 32) {
        // A tile 128x32 (gathered emb rows), 4 float4 per thread
#pragma unroll
        for (int i = 0; i < 4; i++) {
            int r  = (tid >> 3) + i * 32;
            int kq = (tid & 7) * 4;
            float4 v = *(const float4*)(emb + (size_t)idx[r] * IN_DIM + k0 + kq);
            As[r][kq + 0] = v.x; As[r][kq + 1] = v.y;
            As[r][kq + 2] = v.z; As[r][kq + 3] = v.w;
        }
        // B tile 64x32, 2 float4 per thread
#pragma unroll
        for (int i = 0; i < 2; i++) {
            int r  = (tid >> 3) + i * 32;
            int kq = (tid & 7) * 4;
            float4 v = *(const float4*)(W + (size_t)(n0 + r) * IN_DIM + k0 + kq);
            Bs[r][kq + 0] = v.x; Bs[r][kq + 1] = v.y;
            Bs[r][kq + 2] = v.z; Bs[r][kq + 3] = v.w;
        }
        __syncthreads();
#pragma unroll
        for (int k = 0; k < 32; k++) {
            float a[8], bv[4];
#pragma unroll
            for (int i = 0; i < 8; i++) a[i] = As[mt + i][k];
#pragma unroll
            for (int j = 0; j < 4; j++) bv[j] = Bs[nt + j][k];
#pragma unroll
            for (int i = 0; i < 8; i++)
#pragma unroll
                for (int j = 0; j < 4; j++) acc[i][j] += a[i] * bv[j];
        }
        __syncthreads();
    }

    float* outp = (out_sel == 0) ? d_xfp : (out_sel == 1) ? d_xip : d_g;
#pragma unroll
    for (int i = 0; i < 8; i++) {
        int m = m0 + mt + i;
        float4 o;
        o.x = acc[i][0] + bias[n0 + nt + 0];
        o.y = acc[i][1] + bias[n0 + nt + 1];
        o.z = acc[i][2] + bias[n0 + nt + 2];
        o.w = acc[i][3] + bias[n0 + nt + 3];
        if (out_sel == 2) { o.x = sigf(o.x); o.y = sigf(o.y); o.z = sigf(o.z); o.w = sigf(o.w); }
        *(float4*)(outp + (size_t)m * HID + n0 + nt) = o;
    }
}

// ---------------- init c = 0 -------------------------------------------------
__global__ void zero_c_kernel() {
    d_c0[blockIdx.x * 256 + threadIdx.x] = 0.0f;
}

// ---------------- one recurrence step ---------------------------------------
// pre_f = xfp_t + c@Wfh^T ; pre_i = xip_t + c@Wih^T
// c_new = g_t * sigmoid(pre_i) + c * sigmoid(pre_f)
// grid: (HID/32, NBAT/64), 256 threads. Tile: 64(batch) x 32(hidden), K=1024.
__global__ void __launch_bounds__(256) step_kernel(
    int t, const float* __restrict__ Wfh, const float* __restrict__ Wih)
{
    const float* __restrict__ cin  = (t & 1) ? d_c1 : d_c0;
    float* __restrict__       cout = (t & 1) ? d_c0 : d_c1;
    const size_t toff = (size_t)t * (NBAT * HID);
    const float* __restrict__ xfp = d_xfp + toff;
    const float* __restrict__ xip = d_xip + toff;
    const float* __restrict__ gp  = d_g   + toff;

    __shared__ float Cs[64][33];
    __shared__ float Wf[32][33];
    __shared__ float Wi[32][33];

    const int tid = threadIdx.x;
    const int n0 = blockIdx.x * 32;   // hidden
    const int b0 = blockIdx.y * 64;   // batch
    const int mt = (tid >> 4) * 4;    // 0..60 (batch within tile)
    const int nt = (tid & 15) * 2;    // 0..30 (hidden within tile)

    float af[4][2], ai[4][2];
#pragma unroll
    for (int i = 0; i < 4; i++) { af[i][0]=af[i][1]=ai[i][0]=ai[i][1]=0.0f; }

    for (int k0 = 0; k0 < HID; k0 += 32) {
#pragma unroll
        for (int i = 0; i < 2; i++) {
            int r  = (tid >> 3) + i * 32;
            int kq = (tid & 7) * 4;
            float4 v = *(const float4*)(cin + (size_t)(b0 + r) * HID + k0 + kq);
            Cs[r][kq + 0] = v.x; Cs[r][kq + 1] = v.y;
            Cs[r][kq + 2] = v.z; Cs[r][kq + 3] = v.w;
        }
        {
            int r  = tid >> 3;
            int kq = (tid & 7) * 4;
            float4 v = *(const float4*)(Wfh + (size_t)(n0 + r) * HID + k0 + kq);
            Wf[r][kq + 0] = v.x; Wf[r][kq + 1] = v.y;
            Wf[r][kq + 2] = v.z; Wf[r][kq + 3] = v.w;
            float4 u = *(const float4*)(Wih + (size_t)(n0 + r) * HID + k0 + kq);
            Wi[r][kq + 0] = u.x; Wi[r][kq + 1] = u.y;
            Wi[r][kq + 2] = u.z; Wi[r][kq + 3] = u.w;
        }
        __syncthreads();
#pragma unroll
        for (int k = 0; k < 32; k++) {
            float a0 = Cs[mt + 0][k], a1 = Cs[mt + 1][k];
            float a2 = Cs[mt + 2][k], a3 = Cs[mt + 3][k];
            float f0 = Wf[nt + 0][k], f1 = Wf[nt + 1][k];
            float w0 = Wi[nt + 0][k], w1 = Wi[nt + 1][k];
            af[0][0] += a0 * f0; af[0][1] += a0 * f1;
            af[1][0] += a1 * f0; af[1][1] += a1 * f1;
            af[2][0] += a2 * f0; af[2][1] += a2 * f1;
            af[3][0] += a3 * f0; af[3][1] += a3 * f1;
            ai[0][0] += a0 * w0; ai[0][1] += a0 * w1;
            ai[1][0] += a1 * w0; ai[1][1] += a1 * w1;
            ai[2][0] += a2 * w0; ai[2][1] += a2 * w1;
            ai[3][0] += a3 * w0; ai[3][1] += a3 * w1;
        }
        __syncthreads();
    }

#pragma unroll
    for (int i = 0; i < 4; i++) {
        int b = b0 + mt + i;
#pragma unroll
        for (int j = 0; j < 2; j++) {
            size_t off = (size_t)b * HID + n0 + nt + j;
            float f  = sigf(af[i][j] + xfp[off]);
            float ig = sigf(ai[i][j] + xip[off]);
            cout[off] = gp[off] * ig + cin[off] * f;
        }
    }
}

// ---------------- final step o-gate + h -------------------------------------
// pre_o = emb[x[b,511]]@Wox^T + c_511@Woh^T + bo ; h = tanh(c_512)*sigmoid(pre_o)
// After 512 steps: c_511 (carry into last step) = d_c1 (t=511 read buf),
// c_512 (final) = d_c0 (t=511 write buf).
// grid: (HID/64, NBAT/64), 256 threads, 4x4 per thread.
__global__ void __launch_bounds__(256) finalO_kernel(
    const int* __restrict__ x, const float* __restrict__ emb,
    const float* __restrict__ Wox, const float* __restrict__ Woh,
    const float* __restrict__ bo)
{
    __shared__ float As[64][33];
    __shared__ float Bs[64][33];
    __shared__ int   idx[64];
    const int tid = threadIdx.x;
    const int n0 = blockIdx.x * 64;
    const int b0 = blockIdx.y * 64;

    if (tid < 64) idx[tid] = x[(b0 + tid) * SEQ + (SEQ - 1)];
    __syncthreads();

    float acc[4][4];
#pragma unroll
    for (int i = 0; i < 4; i++)
#pragma unroll
        for (int j = 0; j < 4; j++) acc[i][j] = 0.0f;

    const int mt = (tid >> 4) * 4;
    const int nt = (tid & 15) * 4;

    // K = 1024 over c_511 / Woh
    for (int k0 = 0; k0 < HID; k0 += 32) {
#pragma unroll
        for (int i = 0; i < 2; i++) {
            int r  = (tid >> 3) + i * 32;
            int kq = (tid & 7) * 4;
            float4 v = *(const float4*)(d_c1 + (size_t)(b0 + r) * HID + k0 + kq);
            As[r][kq+0]=v.x; As[r][kq+1]=v.y; As[r][kq+2]=v.z; As[r][kq+3]=v.w;
            float4 u = *(const float4*)(Woh + (size_t)(n0 + r) * HID + k0 + kq);
            Bs[r][kq+0]=u.x; Bs[r][kq+1]=u.y; Bs[r][kq+2]=u.z; Bs[r][kq+3]=u.w;
        }
        __syncthreads();
#pragma unroll
        for (int k = 0; k < 32; k++) {
            float a[4], bv[4];
#pragma unroll
            for (int i = 0; i < 4; i++) a[i] = As[mt + i][k];
#pragma unroll
            for (int j = 0; j < 4; j++) bv[j] = Bs[nt + j][k];
#pragma unroll
            for (int i = 0; i < 4; i++)
#pragma unroll
                for (int j = 0; j < 4; j++) acc[i][j] += a[i] * bv[j];
        }
        __syncthreads();
    }
    // K = 256 over emb row / Wox
    for (int k0 = 0; k0 < IN_DIM; k0 += 32) {
#pragma unroll
        for (int i = 0; i < 2; i++) {
            int r  = (tid >> 3) + i * 32;
            int kq = (tid & 7) * 4;
            float4 v = *(const float4*)(emb + (size_t)idx[r] * IN_DIM + k0 + kq);
            As[r][kq+0]=v.x; As[r][kq+1]=v.y; As[r][kq+2]=v.z; As[r][kq+3]=v.w;
            float4 u = *(const float4*)(Wox + (size_t)(n0 + r) * IN_DIM + k0 + kq);
            Bs[r][kq+0]=u.x; Bs[r][kq+1]=u.y; Bs[r][kq+2]=u.z; Bs[r][kq+3]=u.w;
        }
        __syncthreads();
#pragma unroll
        for (int k = 0; k < 32; k++) {
            float a[4], bv[4];
#pragma unroll
            for (int i = 0; i < 4; i++) a[i] = As[mt + i][k];
#pragma unroll
            for (int j = 0; j < 4; j++) bv[j] = Bs[nt + j][k];
#pragma unroll
            for (int i = 0; i < 4; i++)
#pragma unroll
                for (int j = 0; j < 4; j++) acc[i][j] += a[i] * bv[j];
        }
        __syncthreads();
    }

#pragma unroll
    for (int i = 0; i < 4; i++) {
        int b = b0 + mt + i;
#pragma unroll
        for (int j = 0; j < 4; j++) {
            int h = n0 + nt + j;
            size_t off = (size_t)b * HID + h;
            float o = sigf(acc[i][j] + bo[h]);
            d_hT[off] = tanhf(d_c0[off]) * o;
        }
    }
}

// ---------------- projection + log_softmax ----------------------------------
// p[b][n] = h_T[b]@Wph[n] + bp[n]; out = p - logsumexp(p). One block per b.
__global__ void __launch_bounds__(128) proj_kernel(
    const float* __restrict__ Wph, const float* __restrict__ bp,
    float* __restrict__ out)
{
    const int b = blockIdx.x;
    const int n = threadIdx.x;
    __shared__ float hs[HID];
    for (int k = n; k < HID; k += 128) hs[k] = d_hT[(size_t)b * HID + k];
    __syncthreads();

    const float* w = Wph + (size_t)n * HID;
    float acc = bp[n];
#pragma unroll 8
    for (int k = 0; k < HID; k++) acc += hs[k] * w[k];

    __shared__ float red[128];
    red[n] = acc;
    __syncthreads();
    for (int off = 64; off > 0; off >>= 1) {
        if (n < off) red[n] = fmaxf(red[n], red[n + off]);
        __syncthreads();
    }
    float mx = red[0];
    __syncthreads();
    red[n] = __expf(acc - mx);
    __syncthreads();
    for (int off = 64; off > 0; off >>= 1) {
        if (n < off) red[n] += red[n + off];
        __syncthreads();
    }
    float lse = mx + logf(red[0]);
    out[(size_t)b * NCLS + n] = acc - lse;
}

// ---------------- launch ------------------------------------------------------
extern "C" void kernel_launch(void* const* d_in, const int* in_sizes, int n_in,
                              void* d_out, int out_size)
{
    (void)in_sizes; (void)n_in; (void)out_size;
    const int*   x   = (const int*)  d_in[0];
    const float* emb = (const float*)d_in[1];
    const float* Wcx = (const float*)d_in[2];
    const float* bc  = (const float*)d_in[3];
    const float* Wix = (const float*)d_in[4];
    const float* Wih = (const float*)d_in[5];
    const float* bi  = (const float*)d_in[6];
    const float* Wfx = (const float*)d_in[7];
    const float* Wfh = (const float*)d_in[8];
    const float* bf  = (const float*)d_in[9];
    const float* Wox = (const float*)d_in[10];
    const float* Woh = (const float*)d_in[11];
    const float* bo  = (const float*)d_in[12];
    const float* Wph = (const float*)d_in[13];
    const float* bp  = (const float*)d_in[14];
    float* out = (float*)d_out;

    dim3 gA(SEQ * NBAT / 128, HID / 64);
    phaseA_kernel<<<gA, 256>>>(x, emb, Wfx, bf, 0);
    phaseA_kernel<<<gA, 256>>>(x, emb, Wix, bi, 1);
    phaseA_kernel<<<gA, 256>>>(x, emb, Wcx, bc, 2);
    zero_c_kernel<<<NBAT * HID / 256, 256>>>();

    for (int t = 0; t < SEQ; t++)
        step_kernel<<<dim3(HID / 32, NBAT / 64), 256>>>(t, Wfh, Wih);

    finalO_kernel<<<dim3(HID / 64, NBAT / 64), 256>>>(x, emb, Wox, Woh, bo);
    proj_kernel<<<NBAT, 128>>>(Wph, bp, out);
}

// round 7
// speedup vs baseline: 2.0172x; 2.0172x over previous
#include <cuda_runtime.h>
#include <cstdint>
#include <cstddef>

#define SEQ    512
#define NBAT   256
#define IN_DIM 256
#define HID    1024
#define NCLS   128

// ---------------- scratch (no allocation allowed -> device globals) ----------
static __device__ float d_xfp[(size_t)SEQ * NBAT * HID];  // bf + emb@Wfx^T
static __device__ float d_xip[(size_t)SEQ * NBAT * HID];  // bi + emb@Wix^T
static __device__ float d_g  [(size_t)SEQ * NBAT * HID];  // sigmoid(bc + emb@Wcx^T)
static __device__ float d_c0 [NBAT * HID];   // exact c
static __device__ float d_c1 [NBAT * HID];
static __device__ float d_c0t[NBAT * HID];   // tf32-rounded c (mma A operand)
static __device__ float d_c1t[NBAT * HID];
static __device__ float d_hT [NBAT * HID];
// tf32-rounded weights
static __device__ float d_Wfh_r[HID * HID];
static __device__ float d_Wih_r[HID * HID];
static __device__ float d_Wfx_r[HID * IN_DIM];
static __device__ float d_Wix_r[HID * IN_DIM];
static __device__ float d_Wcx_r[HID * IN_DIM];
static __device__ float d_emb_r[NCLS * IN_DIM];

__device__ __forceinline__ float sigf(float x) { return 1.0f / (1.0f + __expf(-x)); }
__device__ __forceinline__ float tf32r(float x) {
    uint32_t r;
    asm("cvt.rna.tf32.f32 %0, %1;" : "=r"(r) : "f"(x));
    return __uint_as_float(r);
}

// ---------------- mma.sync tf32 m16n8k8 (plain sm_103-legal) -----------------
__device__ __forceinline__ void mma8(float* c, const uint32_t* a, const uint32_t* b) {
    asm volatile(
        "mma.sync.aligned.m16n8k8.row.col.f32.tf32.tf32.f32 "
        "{%0,%1,%2,%3}, {%4,%5,%6,%7}, {%8,%9}, {%0,%1,%2,%3};"
        : "+f"(c[0]), "+f"(c[1]), "+f"(c[2]), "+f"(c[3])
        : "r"(a[0]), "r"(a[1]), "r"(a[2]), "r"(a[3]), "r"(b[0]), "r"(b[1]));
}
#define CP16(d, s)  asm volatile("cp.async.cg.shared.global [%0], [%1], 16;" :: "r"(d), "l"(s) : "memory")
#define CP_COMMIT() asm volatile("cp.async.commit_group;" ::: "memory")
#define CP_WAIT1()  asm volatile("cp.async.wait_group 1;" ::: "memory")
#define CP_WAIT0()  asm volatile("cp.async.wait_group 0;" ::: "memory")

__device__ __forceinline__ uint32_t smem_u32(const void* p) {
    uint32_t a;
    asm("{ .reg .u64 t; cvta.to.shared.u64 t, %1; cvt.u32.u64 %0, t; }" : "=r"(a) : "l"(p));
    return a;
}

// ---------------- fused tf32 rounding of all weights/emb ---------------------
// regions (element counts): Wfh 1048576 | Wih 1048576 | Wfx 262144 |
// Wix 262144 | Wcx 262144 | emb 32768   => total 2916352 = 11392 * 256
__global__ void __launch_bounds__(256) round_all(
    const float* __restrict__ Wfh, const float* __restrict__ Wih,
    const float* __restrict__ Wfx, const float* __restrict__ Wix,
    const float* __restrict__ Wcx, const float* __restrict__ emb)
{
    int i = blockIdx.x * 256 + threadIdx.x;
    if (i < 1048576) { d_Wfh_r[i] = tf32r(Wfh[i]); return; }
    i -= 1048576;
    if (i < 1048576) { d_Wih_r[i] = tf32r(Wih[i]); return; }
    i -= 1048576;
    if (i < 262144) { d_Wfx_r[i] = tf32r(Wfx[i]); return; }
    i -= 262144;
    if (i < 262144) { d_Wix_r[i] = tf32r(Wix[i]); return; }
    i -= 262144;
    if (i < 262144) { d_Wcx_r[i] = tf32r(Wcx[i]); return; }
    i -= 262144;
    if (i < 32768) { d_emb_r[i] = tf32r(emb[i]); }
}

// ---------------- init c = 0 -------------------------------------------------
__global__ void zero_c_kernel() {
    int i = blockIdx.x * 256 + threadIdx.x;
    d_c0[i] = 0.0f;
    d_c0t[i] = 0.0f;
}

// ===================== Phase A: 3-gate tf32 mma GEMM ========================
// out[m][h], m = s*256+b; A row = emb_r[x[b][s]] (K=256), B = Wx_r[g] (1024x256)
// CTA tile: M=128, N=64, gate = blockIdx.z. 256 thr = 8 warps (4m x 2n), warp 32x32.
// Dyn smem: As[2][128][36] @0 (36864B), Bs[2][64][36] @36864 (18432B), idx @55296.
#define PA_SMEM (55808)

__global__ void __launch_bounds__(256) phaseA_mma(
    const int* __restrict__ x,
    const float* __restrict__ bfv, const float* __restrict__ biv, const float* __restrict__ bcv)
{
    extern __shared__ __align__(16) char dsm[];
    float (*As)[128][36] = reinterpret_cast<float(*)[128][36]>(dsm);
    float (*Bs)[64][36]  = reinterpret_cast<float(*)[64][36]>(dsm + 36864);
    int* idx = reinterpret_cast<int*>(dsm + 55296);

    const int tid  = threadIdx.x;
    const int wid  = tid >> 5, lane = tid & 31;
    const int m0   = blockIdx.x * 128;
    const int n0   = blockIdx.y * 64;
    const int g    = blockIdx.z;
    const int mbase = (wid >> 1) * 32;
    const int nbase = (wid & 1) * 32;

    const float* __restrict__ Wp =
        (g == 0) ? d_Wfx_r : (g == 1) ? d_Wix_r : d_Wcx_r;
    const float* __restrict__ bp = (g == 0) ? bfv : (g == 1) ? biv : bcv;
    float* __restrict__ outp = (g == 0) ? d_xfp : (g == 1) ? d_xip : d_g;

    if (tid < 128) {
        int m = m0 + tid;
        idx[tid] = x[(m & 255) * SEQ + (m >> 8)];
    }
    __syncthreads();

    const uint32_t sA = smem_u32(As);
    const uint32_t sB = smem_u32(Bs);

    auto load_chunk = [&](int c, int buf) {
        const int k0 = c * 32;
        // A: 128 rows x 8 x16B = 1024 chunks, 4/thread. buf stride 18432B.
#pragma unroll
        for (int i = 0; i < 4; i++) {
            int ch  = tid + i * 256;
            int row = ch >> 3, c16 = ch & 7;
            uint32_t dst = sA + (uint32_t)buf * 18432u + (uint32_t)row * 144u + (uint32_t)c16 * 16u;
            CP16(dst, d_emb_r + (size_t)idx[row] * IN_DIM + k0 + c16 * 4);
        }
        // B: 64 rows x 8 = 512 chunks, 2/thread. buf stride 9216B.
#pragma unroll
        for (int i = 0; i < 2; i++) {
            int ch  = tid + i * 256;
            int row = ch >> 3, c16 = ch & 7;
            uint32_t dst = sB + (uint32_t)buf * 9216u + (uint32_t)row * 144u + (uint32_t)c16 * 16u;
            CP16(dst, Wp + (size_t)(n0 + row) * IN_DIM + k0 + c16 * 4);
        }
        CP_COMMIT();
    };

    float acc[2][4][4];
#pragma unroll
    for (int i = 0; i < 2; i++)
#pragma unroll
        for (int j = 0; j < 4; j++)
#pragma unroll
            for (int r = 0; r < 4; r++) acc[i][j][r] = 0.0f;

    load_chunk(0, 0);
    for (int c = 0; c < 8; c++) {
        if (c + 1 < 8) load_chunk(c + 1, (c + 1) & 1);
        if (c + 1 < 8) { CP_WAIT1(); } else { CP_WAIT0(); }
        __syncthreads();
        const int buf = c & 1;
#pragma unroll
        for (int kk = 0; kk < 4; kk++) {
            const int kc = kk * 8 + (lane & 3);
            uint32_t a[2][4], b[4][2];
#pragma unroll
            for (int mt = 0; mt < 2; mt++) {
                int r = mbase + mt * 16 + (lane >> 2);
                a[mt][0] = __float_as_uint(As[buf][r][kc]);
                a[mt][1] = __float_as_uint(As[buf][r + 8][kc]);
                a[mt][2] = __float_as_uint(As[buf][r][kc + 4]);
                a[mt][3] = __float_as_uint(As[buf][r + 8][kc + 4]);
            }
#pragma unroll
            for (int nt = 0; nt < 4; nt++) {
                int n = nbase + nt * 8 + (lane >> 2);
                b[nt][0] = __float_as_uint(Bs[buf][n][kc]);
                b[nt][1] = __float_as_uint(Bs[buf][n][kc + 4]);
            }
#pragma unroll
            for (int mt = 0; mt < 2; mt++)
#pragma unroll
                for (int nt = 0; nt < 4; nt++) mma8(acc[mt][nt], a[mt], b[nt]);
        }
        __syncthreads();
    }

    // epilogue: direct stores from fragments, +bias (sigmoid for gate 2)
#pragma unroll
    for (int mt = 0; mt < 2; mt++) {
        int mA = m0 + mbase + mt * 16 + (lane >> 2);
#pragma unroll
        for (int nt = 0; nt < 4; nt++) {
            int col = n0 + nbase + nt * 8 + (lane & 3) * 2;
            float b0v = bp[col], b1v = bp[col + 1];
            float2 lo, hi;
            lo.x = acc[mt][nt][0] + b0v; lo.y = acc[mt][nt][1] + b1v;
            hi.x = acc[mt][nt][2] + b0v; hi.y = acc[mt][nt][3] + b1v;
            if (g == 2) { lo.x = sigf(lo.x); lo.y = sigf(lo.y); hi.x = sigf(hi.x); hi.y = sigf(hi.y); }
            *(float2*)(outp + (size_t)mA * HID + col) = lo;
            *(float2*)(outp + (size_t)(mA + 8) * HID + col) = hi;
        }
    }
}

// ===================== Recurrence step: 2-gate tf32 mma GEMM ================
// CTA tile: M=64 (batch), N=32 (hidden), BOTH gates. 8 warps: g=wid>>2,
// quadrant (wid&3): warp 32x16. K=1024, 2-stage cp.async, kc=32.
// Static smem union: mainloop As[2][64][36] (9216B/buf) + Bs[2][2][32][36]
// (9216B/buf, 4608B/gate); epilogue pre[2][64][34] aliases.
struct StepML { float As[2][64][36]; float Bs[2][2][32][36]; };

__global__ void __launch_bounds__(256) step_mma(int t)
{
    __shared__ __align__(16) char smraw[sizeof(StepML)];
    StepML& ml = *reinterpret_cast<StepML*>(smraw);
    float (*pre)[64][34] = reinterpret_cast<float(*)[64][34]>(smraw);

    const int tid  = threadIdx.x;
    const int wid  = tid >> 5, lane = tid & 31;
    const int b0   = blockIdx.x * 64;
    const int n0   = blockIdx.y * 32;
    const int g    = wid >> 2;
    const int wq   = wid & 3;
    const int mbase = (wq >> 1) * 32;
    const int nbase = (wq & 1) * 16;

    const float* __restrict__ cin   = (t & 1) ? d_c1  : d_c0;
    const float* __restrict__ cint  = (t & 1) ? d_c1t : d_c0t;
    float* __restrict__       cout  = (t & 1) ? d_c0  : d_c1;
    float* __restrict__       coutt = (t & 1) ? d_c0t : d_c1t;
    const size_t toff = (size_t)t * (NBAT * HID);

    const uint32_t sA = smem_u32(ml.As);
    const uint32_t sB = smem_u32(ml.Bs);

    auto load_chunk = [&](int c, int buf) {
        const int k0 = c * 32;
        // A: 64 rows x 8 x16B = 512 chunks, 2/thread. buf stride 9216B.
#pragma unroll
        for (int i = 0; i < 2; i++) {
            int ch  = tid + i * 256;
            int row = ch >> 3, c16 = ch & 7;
            uint32_t dst = sA + (uint32_t)buf * 9216u + (uint32_t)row * 144u + (uint32_t)c16 * 16u;
            CP16(dst, cint + (size_t)(b0 + row) * HID + k0 + c16 * 4);
        }
        // B: 2 gates x 32 rows x 8 = 512 chunks, 2/thread.
        // buf stride 9216B (FIXED: was 18432 -> OOB smem write), gate stride 4608B.
#pragma unroll
        for (int i = 0; i < 2; i++) {
            int ch  = tid + i * 256;
            int gg  = ch >> 8, row = (ch >> 3) & 31, c16 = ch & 7;
            const float* src = (gg ? d_Wih_r : d_Wfh_r) + (size_t)(n0 + row) * HID + k0 + c16 * 4;
            uint32_t dst = sB + (uint32_t)buf * 9216u + (uint32_t)gg * 4608u
                              + (uint32_t)row * 144u + (uint32_t)c16 * 16u;
            CP16(dst, src);
        }
        CP_COMMIT();
    };

    float acc[2][2][4];
#pragma unroll
    for (int i = 0; i < 2; i++)
#pragma unroll
        for (int j = 0; j < 2; j++)
#pragma unroll
            for (int r = 0; r < 4; r++) acc[i][j][r] = 0.0f;

    load_chunk(0, 0);
    for (int c = 0; c < 32; c++) {
        if (c + 1 < 32) load_chunk(c + 1, (c + 1) & 1);
        if (c + 1 < 32) { CP_WAIT1(); } else { CP_WAIT0(); }
        __syncthreads();
        const int buf = c & 1;
#pragma unroll
        for (int kk = 0; kk < 4; kk++) {
            const int kc = kk * 8 + (lane & 3);
            uint32_t a[2][4], b[2][2];
#pragma unroll
            for (int mt = 0; mt < 2; mt++) {
                int r = mbase + mt * 16 + (lane >> 2);
                a[mt][0] = __float_as_uint(ml.As[buf][r][kc]);
                a[mt][1] = __float_as_uint(ml.As[buf][r + 8][kc]);
                a[mt][2] = __float_as_uint(ml.As[buf][r][kc + 4]);
                a[mt][3] = __float_as_uint(ml.As[buf][r + 8][kc + 4]);
            }
#pragma unroll
            for (int nt = 0; nt < 2; nt++) {
                int n = nbase + nt * 8 + (lane >> 2);
                b[nt][0] = __float_as_uint(ml.Bs[buf][g][n][kc]);
                b[nt][1] = __float_as_uint(ml.Bs[buf][g][n][kc + 4]);
            }
#pragma unroll
            for (int mt = 0; mt < 2; mt++)
#pragma unroll
                for (int nt = 0; nt < 2; nt++) mma8(acc[mt][nt], a[mt], b[nt]);
        }
        __syncthreads();
    }

    // stage pre-activations to shared (aliases mainloop bufs; loop already synced)
#pragma unroll
    for (int mt = 0; mt < 2; mt++) {
        int m = mbase + mt * 16 + (lane >> 2);
#pragma unroll
        for (int nt = 0; nt < 2; nt++) {
            int n = nbase + nt * 8 + (lane & 3) * 2;
            pre[g][m][n]     = acc[mt][nt][0];
            pre[g][m][n + 1] = acc[mt][nt][1];
            pre[g][m + 8][n]     = acc[mt][nt][2];
            pre[g][m + 8][n + 1] = acc[mt][nt][3];
        }
    }
    __syncthreads();

    // fused pointwise: c_new = g*sig(pre_i + xi) + c*sig(pre_f + xf)
    {
        const int m  = tid >> 2;
        const int nb = (tid & 3) * 8;
        const size_t goff = (size_t)(b0 + m) * HID + n0 + nb;
        const float* __restrict__ xfp = d_xfp + toff;
        const float* __restrict__ xip = d_xip + toff;
        const float* __restrict__ gp  = d_g   + toff;
#pragma unroll
        for (int q = 0; q < 2; q++) {
            const size_t o4 = goff + q * 4;
            float4 xf = *(const float4*)(xfp + o4);
            float4 xi = *(const float4*)(xip + o4);
            float4 gg = *(const float4*)(gp  + o4);
            float4 cc = *(const float4*)(cin + o4);
            const int nn = nb + q * 4;
            float4 cn;
            cn.x = gg.x * sigf(pre[1][m][nn + 0] + xi.x) + cc.x * sigf(pre[0][m][nn + 0] + xf.x);
            cn.y = gg.y * sigf(pre[1][m][nn + 1] + xi.y) + cc.y * sigf(pre[0][m][nn + 1] + xf.y);
            cn.z = gg.z * sigf(pre[1][m][nn + 2] + xi.z) + cc.z * sigf(pre[0][m][nn + 2] + xf.z);
            cn.w = gg.w * sigf(pre[1][m][nn + 3] + xi.w) + cc.w * sigf(pre[0][m][nn + 3] + xf.w);
            *(float4*)(cout + o4) = cn;
            float4 cr;
            cr.x = tf32r(cn.x); cr.y = tf32r(cn.y); cr.z = tf32r(cn.z); cr.w = tf32r(cn.w);
            *(float4*)(coutt + o4) = cr;
        }
    }
}

// ---------------- final step o-gate + h (fp32 SIMT, tiny) --------------------
__global__ void __launch_bounds__(256) finalO_kernel(
    const int* __restrict__ x, const float* __restrict__ emb,
    const float* __restrict__ Wox, const float* __restrict__ Woh,
    const float* __restrict__ bo)
{
    __shared__ float As[64][33];
    __shared__ float Bs[64][33];
    __shared__ int   idx[64];
    const int tid = threadIdx.x;
    const int n0 = blockIdx.x * 64;
    const int b0 = blockIdx.y * 64;

    if (tid < 64) idx[tid] = x[(b0 + tid) * SEQ + (SEQ - 1)];
    __syncthreads();

    float acc[4][4];
#pragma unroll
    for (int i = 0; i < 4; i++)
#pragma unroll
        for (int j = 0; j < 4; j++) acc[i][j] = 0.0f;

    const int mt = (tid >> 4) * 4;
    const int nt = (tid & 15) * 4;

    for (int k0 = 0; k0 < HID; k0 += 32) {
#pragma unroll
        for (int i = 0; i < 2; i++) {
            int r  = (tid >> 3) + i * 32;
            int kq = (tid & 7) * 4;
            float4 v = *(const float4*)(d_c1 + (size_t)(b0 + r) * HID + k0 + kq);
            As[r][kq+0]=v.x; As[r][kq+1]=v.y; As[r][kq+2]=v.z; As[r][kq+3]=v.w;
            float4 u = *(const float4*)(Woh + (size_t)(n0 + r) * HID + k0 + kq);
            Bs[r][kq+0]=u.x; Bs[r][kq+1]=u.y; Bs[r][kq+2]=u.z; Bs[r][kq+3]=u.w;
        }
        __syncthreads();
#pragma unroll
        for (int k = 0; k < 32; k++) {
            float a[4], bv[4];
#pragma unroll
            for (int i = 0; i < 4; i++) a[i] = As[mt + i][k];
#pragma unroll
            for (int j = 0; j < 4; j++) bv[j] = Bs[nt + j][k];
#pragma unroll
            for (int i = 0; i < 4; i++)
#pragma unroll
                for (int j = 0; j < 4; j++) acc[i][j] += a[i] * bv[j];
        }
        __syncthreads();
    }
    for (int k0 = 0; k0 < IN_DIM; k0 += 32) {
#pragma unroll
        for (int i = 0; i < 2; i++) {
            int r  = (tid >> 3) + i * 32;
            int kq = (tid & 7) * 4;
            float4 v = *(const float4*)(emb + (size_t)idx[r] * IN_DIM + k0 + kq);
            As[r][kq+0]=v.x; As[r][kq+1]=v.y; As[r][kq+2]=v.z; As[r][kq+3]=v.w;
            float4 u = *(const float4*)(Wox + (size_t)(n0 + r) * IN_DIM + k0 + kq);
            Bs[r][kq+0]=u.x; Bs[r][kq+1]=u.y; Bs[r][kq+2]=u.z; Bs[r][kq+3]=u.w;
        }
        __syncthreads();
#pragma unroll
        for (int k = 0; k < 32; k++) {
            float a[4], bv[4];
#pragma unroll
            for (int i = 0; i < 4; i++) a[i] = As[mt + i][k];
#pragma unroll
            for (int j = 0; j < 4; j++) bv[j] = Bs[nt + j][k];
#pragma unroll
            for (int i = 0; i < 4; i++)
#pragma unroll
                for (int j = 0; j < 4; j++) acc[i][j] += a[i] * bv[j];
        }
        __syncthreads();
    }

#pragma unroll
    for (int i = 0; i < 4; i++) {
        int b = b0 + mt + i;
#pragma unroll
        for (int j = 0; j < 4; j++) {
            int h = n0 + nt + j;
            size_t off = (size_t)b * HID + h;
            float o = sigf(acc[i][j] + bo[h]);
            d_hT[off] = tanhf(d_c0[off]) * o;
        }
    }
}

// ---------------- projection + log_softmax ----------------------------------
__global__ void __launch_bounds__(128) proj_kernel(
    const float* __restrict__ Wph, const float* __restrict__ bp,
    float* __restrict__ out)
{
    const int b = blockIdx.x;
    const int n = threadIdx.x;
    __shared__ float hs[HID];
    for (int k = n; k < HID; k += 128) hs[k] = d_hT[(size_t)b * HID + k];
    __syncthreads();

    const float* w = Wph + (size_t)n * HID;
    float acc = bp[n];
#pragma unroll 8
    for (int k = 0; k < HID; k++) acc += hs[k] * w[k];

    __shared__ float red[128];
    red[n] = acc;
    __syncthreads();
    for (int off = 64; off > 0; off >>= 1) {
        if (n < off) red[n] = fmaxf(red[n], red[n + off]);
        __syncthreads();
    }
    float mx = red[0];
    __syncthreads();
    red[n] = __expf(acc - mx);
    __syncthreads();
    for (int off = 64; off > 0; off >>= 1) {
        if (n < off) red[n] += red[n + off];
        __syncthreads();
    }
    float lse = mx + logf(red[0]);
    out[(size_t)b * NCLS + n] = acc - lse;
}

// ---------------- launch ------------------------------------------------------
extern "C" void kernel_launch(void* const* d_in, const int* in_sizes, int n_in,
                              void* d_out, int out_size)
{
    (void)in_sizes; (void)n_in; (void)out_size;
    const int*   x   = (const int*)  d_in[0];
    const float* emb = (const float*)d_in[1];
    const float* Wcx = (const float*)d_in[2];
    const float* bc  = (const float*)d_in[3];
    const float* Wix = (const float*)d_in[4];
    const float* Wih = (const float*)d_in[5];
    const float* bi  = (const float*)d_in[6];
    const float* Wfx = (const float*)d_in[7];
    const float* Wfh = (const float*)d_in[8];
    const float* bf  = (const float*)d_in[9];
    const float* Wox = (const float*)d_in[10];
    const float* Woh = (const float*)d_in[11];
    const float* bo  = (const float*)d_in[12];
    const float* Wph = (const float*)d_in[13];
    const float* bp  = (const float*)d_in[14];
    float* out = (float*)d_out;

    cudaFuncSetAttribute(phaseA_mma, cudaFuncAttributeMaxDynamicSharedMemorySize, PA_SMEM);

    // round weights/emb to tf32 grid (total 2916352 elems = 11392 blocks)
    round_all<<<11392, 256>>>(Wfh, Wih, Wfx, Wix, Wcx, emb);

    phaseA_mma<<<dim3(SEQ * NBAT / 128, HID / 64, 3), 256, PA_SMEM>>>(x, bf, bi, bc);
    zero_c_kernel<<<NBAT * HID / 256, 256>>>();

    for (int t = 0; t < SEQ; t++)
        step_mma<<<dim3(NBAT / 64, HID / 32), 256>>>(t);

    finalO_kernel<<<dim3(HID / 64, NBAT / 64), 256>>>(x, emb, Wox, Woh, bo);
    proj_kernel<<<NBAT, 128>>>(Wph, bp, out);
}

// round 9
// speedup vs baseline: 4.5475x; 2.2544x over previous
#include <cuda_runtime.h>
#include <cuda_bf16.h>
#include <cstdint>
#include <cstddef>

#define SEQ    512
#define NBAT   256
#define IN_DIM 256
#define HID    1024
#define NCLS   128

// ---------------- scratch (no allocation allowed -> device globals) ----------
static __device__ float d_xfp[(size_t)SEQ * NBAT * HID];  // bf + emb@Wfx^T
static __device__ float d_xip[(size_t)SEQ * NBAT * HID];  // bi + emb@Wix^T
static __device__ float d_g  [(size_t)SEQ * NBAT * HID];  // sigmoid(bc + emb@Wcx^T)
static __device__ float d_c0 [NBAT * HID];   // exact c
static __device__ float d_c1 [NBAT * HID];
static __device__ __nv_bfloat16 d_cb0[NBAT * HID];  // bf16 c (mma A operand)
static __device__ __nv_bfloat16 d_cb1[NBAT * HID];
static __device__ float d_hT [NBAT * HID];
// rounded weights
static __device__ __nv_bfloat16 d_Wfh_b[HID * HID];
static __device__ __nv_bfloat16 d_Wih_b[HID * HID];
static __device__ float d_Wfx_r[HID * IN_DIM];
static __device__ float d_Wix_r[HID * IN_DIM];
static __device__ float d_Wcx_r[HID * IN_DIM];
static __device__ float d_emb_r[NCLS * IN_DIM];

__device__ __forceinline__ float sigf(float x) { return 1.0f / (1.0f + __expf(-x)); }
__device__ __forceinline__ float tf32r(float x) {
    uint32_t r;
    asm("cvt.rna.tf32.f32 %0, %1;" : "=r"(r) : "f"(x));
    return __uint_as_float(r);
}

// ---------------- mma / ldmatrix / cp.async helpers --------------------------
__device__ __forceinline__ void mma_tf32_8(float* c, const uint32_t* a, const uint32_t* b) {
    asm volatile(
        "mma.sync.aligned.m16n8k8.row.col.f32.tf32.tf32.f32 "
        "{%0,%1,%2,%3}, {%4,%5,%6,%7}, {%8,%9}, {%0,%1,%2,%3};"
        : "+f"(c[0]), "+f"(c[1]), "+f"(c[2]), "+f"(c[3])
        : "r"(a[0]), "r"(a[1]), "r"(a[2]), "r"(a[3]), "r"(b[0]), "r"(b[1]));
}
__device__ __forceinline__ void mma_bf16_16(float* c, const uint32_t* a,
                                            uint32_t b0, uint32_t b1) {
    asm volatile(
        "mma.sync.aligned.m16n8k16.row.col.f32.bf16.bf16.f32 "
        "{%0,%1,%2,%3}, {%4,%5,%6,%7}, {%8,%9}, {%0,%1,%2,%3};"
        : "+f"(c[0]), "+f"(c[1]), "+f"(c[2]), "+f"(c[3])
        : "r"(a[0]), "r"(a[1]), "r"(a[2]), "r"(a[3]), "r"(b0), "r"(b1));
}
__device__ __forceinline__ void ldmx4(uint32_t* r, uint32_t addr) {
    asm volatile("ldmatrix.sync.aligned.m8n8.x4.shared.b16 {%0,%1,%2,%3}, [%4];"
        : "=r"(r[0]), "=r"(r[1]), "=r"(r[2]), "=r"(r[3]) : "r"(addr));
}
#define CP16(d, s)  asm volatile("cp.async.cg.shared.global [%0], [%1], 16;" :: "r"(d), "l"(s) : "memory")
#define CP_COMMIT() asm volatile("cp.async.commit_group;" ::: "memory")
#define CP_WAIT2()  asm volatile("cp.async.wait_group 2;" ::: "memory")
#define CP_WAIT1()  asm volatile("cp.async.wait_group 1;" ::: "memory")
#define CP_WAIT0()  asm volatile("cp.async.wait_group 0;" ::: "memory")

__device__ __forceinline__ uint32_t smem_u32(const void* p) {
    uint32_t a;
    asm("{ .reg .u64 t; cvta.to.shared.u64 t, %1; cvt.u32.u64 %0, t; }" : "=r"(a) : "l"(p));
    return a;
}

// ---------------- fused rounding: Wfh/Wih -> bf16, x-weights/emb -> tf32 ----
// bf16: Wfh 1048576 | Wih 1048576 ; tf32: Wfx 262144 | Wix 262144 |
// Wcx 262144 | emb 32768. total 2916352 = 11392*256
__global__ void __launch_bounds__(256) round_all(
    const float* __restrict__ Wfh, const float* __restrict__ Wih,
    const float* __restrict__ Wfx, const float* __restrict__ Wix,
    const float* __restrict__ Wcx, const float* __restrict__ emb)
{
    int i = blockIdx.x * 256 + threadIdx.x;
    if (i < 1048576) { d_Wfh_b[i] = __float2bfloat16_rn(Wfh[i]); return; }
    i -= 1048576;
    if (i < 1048576) { d_Wih_b[i] = __float2bfloat16_rn(Wih[i]); return; }
    i -= 1048576;
    if (i < 262144) { d_Wfx_r[i] = tf32r(Wfx[i]); return; }
    i -= 262144;
    if (i < 262144) { d_Wix_r[i] = tf32r(Wix[i]); return; }
    i -= 262144;
    if (i < 262144) { d_Wcx_r[i] = tf32r(Wcx[i]); return; }
    i -= 262144;
    if (i < 32768) { d_emb_r[i] = tf32r(emb[i]); }
}

// ---------------- init c = 0 -------------------------------------------------
__global__ void zero_c_kernel() {
    int i = blockIdx.x * 256 + threadIdx.x;
    d_c0[i] = 0.0f;
    d_cb0[i] = __float2bfloat16_rn(0.0f);
}

// ===================== Phase A: 3-gate tf32 mma GEMM (unchanged) ============
#define PA_SMEM (55808)

__global__ void __launch_bounds__(256) phaseA_mma(
    const int* __restrict__ x,
    const float* __restrict__ bfv, const float* __restrict__ biv, const float* __restrict__ bcv)
{
    extern __shared__ __align__(16) char dsm[];
    float (*As)[128][36] = reinterpret_cast<float(*)[128][36]>(dsm);
    float (*Bs)[64][36]  = reinterpret_cast<float(*)[64][36]>(dsm + 36864);
    int* idx = reinterpret_cast<int*>(dsm + 55296);

    const int tid  = threadIdx.x;
    const int wid  = tid >> 5, lane = tid & 31;
    const int m0   = blockIdx.x * 128;
    const int n0   = blockIdx.y * 64;
    const int g    = blockIdx.z;
    const int mbase = (wid >> 1) * 32;
    const int nbase = (wid & 1) * 32;

    const float* __restrict__ Wp =
        (g == 0) ? d_Wfx_r : (g == 1) ? d_Wix_r : d_Wcx_r;
    const float* __restrict__ bp = (g == 0) ? bfv : (g == 1) ? biv : bcv;
    float* __restrict__ outp = (g == 0) ? d_xfp : (g == 1) ? d_xip : d_g;

    if (tid < 128) {
        int m = m0 + tid;
        idx[tid] = x[(m & 255) * SEQ + (m >> 8)];
    }
    __syncthreads();

    const uint32_t sA = smem_u32(As);
    const uint32_t sB = smem_u32(Bs);

    auto load_chunk = [&](int c, int buf) {
        const int k0 = c * 32;
#pragma unroll
        for (int i = 0; i < 4; i++) {
            int ch  = tid + i * 256;
            int row = ch >> 3, c16 = ch & 7;
            uint32_t dst = sA + (uint32_t)buf * 18432u + (uint32_t)row * 144u + (uint32_t)c16 * 16u;
            CP16(dst, d_emb_r + (size_t)idx[row] * IN_DIM + k0 + c16 * 4);
        }
#pragma unroll
        for (int i = 0; i < 2; i++) {
            int ch  = tid + i * 256;
            int row = ch >> 3, c16 = ch & 7;
            uint32_t dst = sB + (uint32_t)buf * 9216u + (uint32_t)row * 144u + (uint32_t)c16 * 16u;
            CP16(dst, Wp + (size_t)(n0 + row) * IN_DIM + k0 + c16 * 4);
        }
        CP_COMMIT();
    };

    float acc[2][4][4];
#pragma unroll
    for (int i = 0; i < 2; i++)
#pragma unroll
        for (int j = 0; j < 4; j++)
#pragma unroll
            for (int r = 0; r < 4; r++) acc[i][j][r] = 0.0f;

    load_chunk(0, 0);
    for (int c = 0; c < 8; c++) {
        if (c + 1 < 8) load_chunk(c + 1, (c + 1) & 1);
        if (c + 1 < 8) { CP_WAIT1(); } else { CP_WAIT0(); }
        __syncthreads();
        const int buf = c & 1;
#pragma unroll
        for (int kk = 0; kk < 4; kk++) {
            const int kc = kk * 8 + (lane & 3);
            uint32_t a[2][4], b[4][2];
#pragma unroll
            for (int mt = 0; mt < 2; mt++) {
                int r = mbase + mt * 16 + (lane >> 2);
                a[mt][0] = __float_as_uint(As[buf][r][kc]);
                a[mt][1] = __float_as_uint(As[buf][r + 8][kc]);
                a[mt][2] = __float_as_uint(As[buf][r][kc + 4]);
                a[mt][3] = __float_as_uint(As[buf][r + 8][kc + 4]);
            }
#pragma unroll
            for (int nt = 0; nt < 4; nt++) {
                int n = nbase + nt * 8 + (lane >> 2);
                b[nt][0] = __float_as_uint(Bs[buf][n][kc]);
                b[nt][1] = __float_as_uint(Bs[buf][n][kc + 4]);
            }
#pragma unroll
            for (int mt = 0; mt < 2; mt++)
#pragma unroll
                for (int nt = 0; nt < 4; nt++) mma_tf32_8(acc[mt][nt], a[mt], b[nt]);
        }
        __syncthreads();
    }

#pragma unroll
    for (int mt = 0; mt < 2; mt++) {
        int mA = m0 + mbase + mt * 16 + (lane >> 2);
#pragma unroll
        for (int nt = 0; nt < 4; nt++) {
            int col = n0 + nbase + nt * 8 + (lane & 3) * 2;
            float b0v = bp[col], b1v = bp[col + 1];
            float2 lo, hi;
            lo.x = acc[mt][nt][0] + b0v; lo.y = acc[mt][nt][1] + b1v;
            hi.x = acc[mt][nt][2] + b0v; hi.y = acc[mt][nt][3] + b1v;
            if (g == 2) { lo.x = sigf(lo.x); lo.y = sigf(lo.y); hi.x = sigf(hi.x); hi.y = sigf(hi.y); }
            *(float2*)(outp + (size_t)mA * HID + col) = lo;
            *(float2*)(outp + (size_t)(mA + 8) * HID + col) = hi;
        }
    }
}

// ===================== Recurrence step: bf16 mma + ldmatrix =================
// CTA tile: M=64 (batch), N=64 (2 gates x 32 hidden). 8 warps: gate=wid>>2,
// quadrant wq=wid&3: warp M=32 (wq>>1), N=16 (wq&1). K=1024, 32 chunks of 32,
// 4-stage cp.async, one __syncthreads per chunk.
// SMEM: A[4 stages][64 rows][80B] = 20480B, B same = 20480B (B rows = gate*32+n).
// Row = 64B data (32 bf16) + 16B pad -> conflict-free ldmatrix.
// Epilogue pre[2][64][34] f32 aliases the mainloop buffers.
#define ST_STAGE_BYTES 5120
struct StepSM { uint8_t A[4 * ST_STAGE_BYTES]; uint8_t B[4 * ST_STAGE_BYTES]; };

__global__ void __launch_bounds__(256) step_mma(int t)
{
    __shared__ __align__(16) char smraw[sizeof(StepSM)];
    StepSM& sm = *reinterpret_cast<StepSM*>(smraw);
    float (*pre)[64][34] = reinterpret_cast<float(*)[64][34]>(smraw);

    const int tid  = threadIdx.x;
    const int wid  = tid >> 5, lane = tid & 31;
    const int b0   = blockIdx.x * 64;
    const int n0   = blockIdx.y * 32;
    const int g    = wid >> 2;
    const int wq   = wid & 3;
    const int mbase = (wq >> 1) * 32;
    const int nwarp = (wq & 1) * 16;          // within gate's 32 cols

    const float* __restrict__ cin  = (t & 1) ? d_c1  : d_c0;
    const __nv_bfloat16* __restrict__ cbin = (t & 1) ? d_cb1 : d_cb0;
    float* __restrict__          cout  = (t & 1) ? d_c0  : d_c1;
    __nv_bfloat16* __restrict__  coutb = (t & 1) ? d_cb0 : d_cb1;
    const size_t toff = (size_t)t * (NBAT * HID);

    const uint32_t sA = smem_u32(sm.A);
    const uint32_t sB = smem_u32(sm.B);

    // loader: 512 x 16B chunks per stage (A 256: 64 rows x 4; B 256), 2/thread
    auto load_chunk = [&](int c, int st) {
        const int k0 = c * 32;
#pragma unroll
        for (int i = 0; i < 2; i++) {
            int ch = tid + i * 256;            // 0..511
            int c16 = ch & 3;
            if (ch < 256) {
                int row = ch >> 2;
                uint32_t dst = sA + (uint32_t)st * ST_STAGE_BYTES + (uint32_t)row * 80u + (uint32_t)c16 * 16u;
                CP16(dst, cbin + (size_t)(b0 + row) * HID + k0 + c16 * 8);
            } else {
                int row = (ch - 256) >> 2;     // 0..63 ; gate = row>>5
                const __nv_bfloat16* src = ((row >> 5) ? d_Wih_b : d_Wfh_b)
                    + (size_t)(n0 + (row & 31)) * HID + k0 + c16 * 8;
                uint32_t dst = sB + (uint32_t)st * ST_STAGE_BYTES + (uint32_t)row * 80u + (uint32_t)c16 * 16u;
                CP16(dst, src);
            }
        }
        CP_COMMIT();
    };

    float acc[2][2][4];
#pragma unroll
    for (int i = 0; i < 2; i++)
#pragma unroll
        for (int j = 0; j < 2; j++)
#pragma unroll
            for (int r = 0; r < 4; r++) acc[i][j][r] = 0.0f;

    load_chunk(0, 0); load_chunk(1, 1); load_chunk(2, 2);

    const int brow0 = g * 32 + nwarp;          // warp's 16 B-rows start
    const uint32_t lquad = (lane & 15);
    const uint32_t lhalf = (lane >> 4) * 16u;  // 16B half select

    for (int c = 0; c < 32; c++) {
        if (c <= 29)      { CP_WAIT2(); }
        else if (c == 30) { CP_WAIT1(); }
        else              { CP_WAIT0(); }
        __syncthreads();
        if (c + 3 < 32) load_chunk(c + 3, (c + 3) & 3);

        const uint32_t st = (uint32_t)(c & 3) * ST_STAGE_BYTES;
#pragma unroll
        for (int kk = 0; kk < 2; kk++) {
            uint32_t a[2][4], b[4];
#pragma unroll
            for (int mt = 0; mt < 2; mt++) {
                uint32_t addr = sA + st + (uint32_t)(mbase + mt * 16 + lquad) * 80u
                              + (uint32_t)kk * 32u + lhalf;
                ldmx4(a[mt], addr);
            }
            {
                uint32_t addr = sB + st + (uint32_t)(brow0 + lquad) * 80u
                              + (uint32_t)kk * 32u + lhalf;
                ldmx4(b, addr);
            }
#pragma unroll
            for (int mt = 0; mt < 2; mt++) {
                mma_bf16_16(acc[mt][0], a[mt], b[0], b[2]);
                mma_bf16_16(acc[mt][1], a[mt], b[1], b[3]);
            }
        }
    }
    __syncthreads();   // all reads of smem tiles done before aliasing as `pre`

    // stage pre-activations to shared
#pragma unroll
    for (int mt = 0; mt < 2; mt++) {
        int m = mbase + mt * 16 + (lane >> 2);
#pragma unroll
        for (int nt = 0; nt < 2; nt++) {
            int n = nwarp + nt * 8 + (lane & 3) * 2;
            pre[g][m][n]         = acc[mt][nt][0];
            pre[g][m][n + 1]     = acc[mt][nt][1];
            pre[g][m + 8][n]     = acc[mt][nt][2];
            pre[g][m + 8][n + 1] = acc[mt][nt][3];
        }
    }
    __syncthreads();

    // fused pointwise: c_new = g*sig(pre_i + xi) + c*sig(pre_f + xf)
    {
        const int m  = tid >> 2;
        const int nb = (tid & 3) * 8;
        const size_t goff = (size_t)(b0 + m) * HID + n0 + nb;
        const float* __restrict__ xfp = d_xfp + toff;
        const float* __restrict__ xip = d_xip + toff;
        const float* __restrict__ gp  = d_g   + toff;
#pragma unroll
        for (int q = 0; q < 2; q++) {
            const size_t o4 = goff + q * 4;
            float4 xf = *(const float4*)(xfp + o4);
            float4 xi = *(const float4*)(xip + o4);
            float4 gg = *(const float4*)(gp  + o4);
            float4 cc = *(const float4*)(cin + o4);
            const int nn = nb + q * 4;
            float4 cn;
            cn.x = gg.x * sigf(pre[1][m][nn + 0] + xi.x) + cc.x * sigf(pre[0][m][nn + 0] + xf.x);
            cn.y = gg.y * sigf(pre[1][m][nn + 1] + xi.y) + cc.y * sigf(pre[0][m][nn + 1] + xf.y);
            cn.z = gg.z * sigf(pre[1][m][nn + 2] + xi.z) + cc.z * sigf(pre[0][m][nn + 2] + xf.z);
            cn.w = gg.w * sigf(pre[1][m][nn + 3] + xi.w) + cc.w * sigf(pre[0][m][nn + 3] + xf.w);
            *(float4*)(cout + o4) = cn;
            __nv_bfloat162* cb = (__nv_bfloat162*)(coutb + o4);
            cb[0] = __nv_bfloat162(__float2bfloat16_rn(cn.x), __float2bfloat16_rn(cn.y));
            cb[1] = __nv_bfloat162(__float2bfloat16_rn(cn.z), __float2bfloat16_rn(cn.w));
        }
    }
}

// ---------------- final step o-gate + h (fp32 SIMT, tiny) --------------------
__global__ void __launch_bounds__(256) finalO_kernel(
    const int* __restrict__ x, const float* __restrict__ emb,
    const float* __restrict__ Wox, const float* __restrict__ Woh,
    const float* __restrict__ bo)
{
    __shared__ float As[64][33];
    __shared__ float Bs[64][33];
    __shared__ int   idx[64];
    const int tid = threadIdx.x;
    const int n0 = blockIdx.x * 64;
    const int b0 = blockIdx.y * 64;

    if (tid < 64) idx[tid] = x[(b0 + tid) * SEQ + (SEQ - 1)];
    __syncthreads();

    float acc[4][4];
#pragma unroll
    for (int i = 0; i < 4; i++)
#pragma unroll
        for (int j = 0; j < 4; j++) acc[i][j] = 0.0f;

    const int mt = (tid >> 4) * 4;
    const int nt = (tid & 15) * 4;

    for (int k0 = 0; k0 < HID; k0 += 32) {
#pragma unroll
        for (int i = 0; i < 2; i++) {
            int r  = (tid >> 3) + i * 32;
            int kq = (tid & 7) * 4;
            float4 v = *(const float4*)(d_c1 + (size_t)(b0 + r) * HID + k0 + kq);
            As[r][kq+0]=v.x; As[r][kq+1]=v.y; As[r][kq+2]=v.z; As[r][kq+3]=v.w;
            float4 u = *(const float4*)(Woh + (size_t)(n0 + r) * HID + k0 + kq);
            Bs[r][kq+0]=u.x; Bs[r][kq+1]=u.y; Bs[r][kq+2]=u.z; Bs[r][kq+3]=u.w;
        }
        __syncthreads();
#pragma unroll
        for (int k = 0; k < 32; k++) {
            float a[4], bv[4];
#pragma unroll
            for (int i = 0; i < 4; i++) a[i] = As[mt + i][k];
#pragma unroll
            for (int j = 0; j < 4; j++) bv[j] = Bs[nt + j][k];
#pragma unroll
            for (int i = 0; i < 4; i++)
#pragma unroll
                for (int j = 0; j < 4; j++) acc[i][j] += a[i] * bv[j];
        }
        __syncthreads();
    }
    for (int k0 = 0; k0 < IN_DIM; k0 += 32) {
#pragma unroll
        for (int i = 0; i < 2; i++) {
            int r  = (tid >> 3) + i * 32;
            int kq = (tid & 7) * 4;
            float4 v = *(const float4*)(emb + (size_t)idx[r] * IN_DIM + k0 + kq);
            As[r][kq+0]=v.x; As[r][kq+1]=v.y; As[r][kq+2]=v.z; As[r][kq+3]=v.w;
            float4 u = *(const float4*)(Wox + (size_t)(n0 + r) * IN_DIM + k0 + kq);
            Bs[r][kq+0]=u.x; Bs[r][kq+1]=u.y; Bs[r][kq+2]=u.z; Bs[r][kq+3]=u.w;
        }
        __syncthreads();
#pragma unroll
        for (int k = 0; k < 32; k++) {
            float a[4], bv[4];
#pragma unroll
            for (int i = 0; i < 4; i++) a[i] = As[mt + i][k];
#pragma unroll
            for (int j = 0; j < 4; j++) bv[j] = Bs[nt + j][k];
#pragma unroll
            for (int i = 0; i < 4; i++)
#pragma unroll
                for (int j = 0; j < 4; j++) acc[i][j] += a[i] * bv[j];
        }
        __syncthreads();
    }

#pragma unroll
    for (int i = 0; i < 4; i++) {
        int b = b0 + mt + i;
#pragma unroll
        for (int j = 0; j < 4; j++) {
            int h = n0 + nt + j;
            size_t off = (size_t)b * HID + h;
            float o = sigf(acc[i][j] + bo[h]);
            d_hT[off] = tanhf(d_c0[off]) * o;
        }
    }
}

// ---------------- projection + log_softmax ----------------------------------
__global__ void __launch_bounds__(128) proj_kernel(
    const float* __restrict__ Wph, const float* __restrict__ bp,
    float* __restrict__ out)
{
    const int b = blockIdx.x;
    const int n = threadIdx.x;
    __shared__ float hs[HID];
    for (int k = n; k < HID; k += 128) hs[k] = d_hT[(size_t)b * HID + k];
    __syncthreads();

    const float* w = Wph + (size_t)n * HID;
    float acc = bp[n];
#pragma unroll 8
    for (int k = 0; k < HID; k++) acc += hs[k] * w[k];

    __shared__ float red[128];
    red[n] = acc;
    __syncthreads();
    for (int off = 64; off > 0; off >>= 1) {
        if (n < off) red[n] = fmaxf(red[n], red[n + off]);
        __syncthreads();
    }
    float mx = red[0];
    __syncthreads();
    red[n] = __expf(acc - mx);
    __syncthreads();
    for (int off = 64; off > 0; off >>= 1) {
        if (n < off) red[n] += red[n + off];
        __syncthreads();
    }
    float lse = mx + logf(red[0]);
    out[(size_t)b * NCLS + n] = acc - lse;
}

// ---------------- launch ------------------------------------------------------
extern "C" void kernel_launch(void* const* d_in, const int* in_sizes, int n_in,
                              void* d_out, int out_size)
{
    (void)in_sizes; (void)n_in; (void)out_size;
    const int*   x   = (const int*)  d_in[0];
    const float* emb = (const float*)d_in[1];
    const float* Wcx = (const float*)d_in[2];
    const float* bc  = (const float*)d_in[3];
    const float* Wix = (const float*)d_in[4];
    const float* Wih = (const float*)d_in[5];
    const float* bi  = (const float*)d_in[6];
    const float* Wfx = (const float*)d_in[7];
    const float* Wfh = (const float*)d_in[8];
    const float* bf  = (const float*)d_in[9];
    const float* Wox = (const float*)d_in[10];
    const float* Woh = (const float*)d_in[11];
    const float* bo  = (const float*)d_in[12];
    const float* Wph = (const float*)d_in[13];
    const float* bp  = (const float*)d_in[14];
    float* out = (float*)d_out;

    cudaFuncSetAttribute(phaseA_mma, cudaFuncAttributeMaxDynamicSharedMemorySize, PA_SMEM);

    round_all<<<11392, 256>>>(Wfh, Wih, Wfx, Wix, Wcx, emb);

    phaseA_mma<<<dim3(SEQ * NBAT / 128, HID / 64, 3), 256, PA_SMEM>>>(x, bf, bi, bc);
    zero_c_kernel<<<NBAT * HID / 256, 256>>>();

    for (int t = 0; t < SEQ; t++)
        step_mma<<<dim3(NBAT / 64, HID / 32), 256>>>(t);

    finalO_kernel<<<dim3(HID / 64, NBAT / 64), 256>>>(x, emb, Wox, Woh, bo);
    proj_kernel<<<NBAT, 128>>>(Wph, bp, out);
}